// round 13
// baseline (speedup 1.0000x reference)
#include <cuda_runtime.h>

#define NPTS 2000000
#define NG   16384

typedef unsigned long long u64;

// Scratch (device globals: allocation-free, graph-capturable)
__device__ float g_xe[NPTS * 5];        // per-point embedding
__device__ float g_aggr[NG * 5];        // segment sum of xe
__device__ float g_pooled[NG * 32];     // segment sum of xo
__device__ u64   g_hbias[NG * 20];      // per-graph W1b·xg, packed pairs
__device__ u64   g_stage[1820];         // staging image for the constant bank

// One constant bank; regions 16B-aligned
__constant__ __align__(16) u64 cAll[1820];
#define WE1  (cAll + 0)      // [3][40] packed over outputs            (60)
#define WE2T (cAll + 60)     // transposed: [5 outputs][20 pairs]      (100)
#define WG1  (cAll + 160)    // [5][40]                                (100)
#define WG2  (cAll + 260)    // [40][4]                                (80)
#define WO1  (cAll + 340)    // [9][40]: rows 0-4 k_out, 5-8 k_glob    (180)
#define WO2T (cAll + 520)    // transposed: [32 outputs][20 pairs]     (640)
#define WD1  (cAll + 1160)   // [32][40]                               (640)
#define WD2  (cAll + 1800)   // [40][1]                                (20)

// ---------- packed f32x2 helpers ----------
__device__ __forceinline__ u64 pk2(float lo, float hi) {
    u64 r; asm("mov.b64 %0, {%1, %2};" : "=l"(r) : "f"(lo), "f"(hi)); return r;
}
__device__ __forceinline__ void up2(u64 v, float& lo, float& hi) {
    asm("mov.b64 {%0, %1}, %2;" : "=f"(lo), "=f"(hi) : "l"(v));
}
__device__ __forceinline__ u64 ffma2(u64 a, u64 b, u64 c) {
    u64 d; asm("fma.rn.f32x2 %0, %1, %2, %3;" : "=l"(d) : "l"(a), "l"(b), "l"(c)); return d;
}
__device__ __forceinline__ u64 mul2(u64 a, u64 b) {
    u64 d; asm("mul.rn.f32x2 %0, %1, %2;" : "=l"(d) : "l"(a), "l"(b)); return d;
}
__device__ __forceinline__ u64 add2(u64 a, u64 b) {
    u64 d; asm("add.rn.f32x2 %0, %1, %2;" : "=l"(d) : "l"(a), "l"(b)); return d;
}
// scalar leaky_relu (exact)
__device__ __forceinline__ float lrelu(float v) { return fmaxf(v, 0.01f * v); }
// packed leaky_relu: 0.505x + 0.495|x| (== lrelu to ~6e-6 rel)
__device__ __forceinline__ u64 plrelu2(u64 v) {
    u64 cA = pk2(0.505f, 0.505f), cB = pk2(0.495f, 0.495f);
    u64 av = v & 0x7FFFFFFF7FFFFFFFULL;
    return ffma2(av, cB, mul2(v, cA));
}
// 16B constant load helper
__device__ __forceinline__ ulonglong2 ldc2(const u64* p) {
    return *(const ulonglong2*)p;
}

// ---------- pre: zero g_aggr + build full weight image in g_stage ----------
__global__ void __launch_bounds__(256) k_pre(const float* __restrict__ We1,
                                             const float* __restrict__ We2,
                                             const float* __restrict__ Wg1,
                                             const float* __restrict__ Wg2,
                                             const float* __restrict__ Wo1,
                                             const float* __restrict__ Wo2,
                                             const float* __restrict__ Wd1,
                                             const float* __restrict__ Wd2) {
    int i = blockIdx.x * 256 + threadIdx.x;
    if (i < NG * 5 / 4) ((float4*)g_aggr)[i] = make_float4(0.f, 0.f, 0.f, 0.f);
    if (i < 1820) {
        u64 v;
        if (i < 60)        v = ((const u64*)We1)[i];
        else if (i < 160)  { int t = i - 60;  int j = t / 20, q = t % 20;
                             v = pk2(We2[(2 * q) * 5 + j], We2[(2 * q + 1) * 5 + j]); }
        else if (i < 260)  v = ((const u64*)Wg1)[i - 160];
        else if (i < 340)  v = ((const u64*)Wg2)[i - 260];
        else if (i < 520)  v = ((const u64*)Wo1)[i - 340];
        else if (i < 1160) { int t = i - 520; int j = t / 20, q = t % 20;
                             v = pk2(Wo2[(2 * q) * 32 + j], Wo2[(2 * q + 1) * 32 + j]); }
        else if (i < 1800) v = ((const u64*)Wd1)[i - 1160];
        else               v = ((const u64*)Wd2)[i - 1800];
        g_stage[i] = v;
    }
}

// =====================================================================
// Pass 1: xe = ffn(x, We1, We2); store xe; segment-sum -> g_aggr.  P=2.
// =====================================================================
__global__ void __launch_bounds__(256, 2) k_emb(const float* __restrict__ x,
                                                const int* __restrict__ batch) {
    int tid = threadIdx.x;
    int t = blockIdx.x * 256 + tid;
    int i0 = t * 2;
    if (i0 >= NPTS) return;   // NPTS % 64 == 0 -> surviving warps are full

    const float2* xp = (const float2*)(x + i0 * 3);
    float2 p0 = xp[0], p1 = xp[1], p2 = xp[2];
    float inA[3] = {p0.x, p0.y, p1.x};
    float inB[3] = {p1.y, p2.x, p2.y};

    // hidden 3 -> 40 (packed over outputs)
    u64 hA[20], hB[20];
#pragma unroll
    for (int q = 0; q < 20; q++) { hA[q] = 0ULL; hB[q] = 0ULL; }
#pragma unroll
    for (int k = 0; k < 3; k++) {
        u64 aA = pk2(inA[k], inA[k]);
        u64 aB = pk2(inB[k], inB[k]);
#pragma unroll
        for (int q = 0; q < 20; q += 2) {
            ulonglong2 w = ldc2(&WE1[k * 20 + q]);
            hA[q]     = ffma2(aA, w.x, hA[q]);
            hA[q + 1] = ffma2(aA, w.y, hA[q + 1]);
            hB[q]     = ffma2(aB, w.x, hB[q]);
            hB[q + 1] = ffma2(aB, w.y, hB[q + 1]);
        }
    }
#pragma unroll
    for (int q = 0; q < 20; q++) { hA[q] = plrelu2(hA[q]); hB[q] = plrelu2(hB[q]); }

    // out 40 -> 5: packed dot over hidden pairs (transposed weights)
    float xeA[5], xeB[5];
#pragma unroll
    for (int j = 0; j < 5; j++) {
        u64 aA = 0ULL, aB = 0ULL;
#pragma unroll
        for (int q = 0; q < 20; q += 2) {
            ulonglong2 w = ldc2(&WE2T[j * 20 + q]);
            aA = ffma2(hA[q], w.x, aA); aA = ffma2(hA[q + 1], w.y, aA);
            aB = ffma2(hB[q], w.x, aB); aB = ffma2(hB[q + 1], w.y, aB);
        }
        float lo, hi;
        up2(aA, lo, hi); xeA[j] = lrelu(lo + hi);
        up2(aB, lo, hi); xeB[j] = lrelu(lo + hi);
    }

    // store xe for both points: 10 consecutive floats -> 5 STG.64
    {
        float2* xo = (float2*)(g_xe + i0 * 5);
        xo[0] = make_float2(xeA[0], xeA[1]);
        xo[1] = make_float2(xeA[2], xeA[3]);
        xo[2] = make_float2(xeA[4], xeB[0]);
        xo[3] = make_float2(xeB[1], xeB[2]);
        xo[4] = make_float2(xeB[3], xeB[4]);
    }

    // segmented sum -> g_aggr (channels (0,1),(2,3) packed, 4 scalar)
    int2 bb = *(const int2*)(batch + i0);
    int bA = bb.x, bB = bb.y;
    bool same = (bA == bB);
    unsigned peers = __match_any_sync(0xffffffffu, bA);
    int lane = tid & 31;
    int hiL = 31 - __clz(peers);
    bool leader = (lane == __ffs(peers) - 1);

    u64 m01 = pk2(xeA[0], xeA[1]);
    u64 m23 = pk2(xeA[2], xeA[3]);
    float m4 = xeA[4];
    if (same) {
        m01 = add2(m01, pk2(xeB[0], xeB[1]));
        m23 = add2(m23, pk2(xeB[2], xeB[3]));
        m4 += xeB[4];
    }
#pragma unroll
    for (int d = 1; d < 32; d <<= 1) {
        u64 s0 = __shfl_down_sync(0xffffffffu, m01, d);
        u64 s1 = __shfl_down_sync(0xffffffffu, m23, d);
        float s2 = __shfl_down_sync(0xffffffffu, m4, d);
        if (lane + d <= hiL) { m01 = add2(m01, s0); m23 = add2(m23, s1); m4 += s2; }
    }
    if (leader) {
        float a0, a1; up2(m01, a0, a1);
        float a2, a3; up2(m23, a2, a3);
        atomicAdd(&g_aggr[bA * 5 + 0], a0);
        atomicAdd(&g_aggr[bA * 5 + 1], a1);
        atomicAdd(&g_aggr[bA * 5 + 2], a2);
        atomicAdd(&g_aggr[bA * 5 + 3], a3);
        atomicAdd(&g_aggr[bA * 5 + 4], m4);
    }
    if (!same) {
#pragma unroll
        for (int c = 0; c < 5; c++) atomicAdd(&g_aggr[bB * 5 + c], xeB[c]);
    }
}

// =====================================================================
// Pass 2: xg = ffn(x_aggr, Wg1, Wg2); hbias = W1b·xg -> g_hbias.
// Also zeroes g_pooled.
// =====================================================================
__global__ void __launch_bounds__(256) k_glob() {
    int g = blockIdx.x * 256 + threadIdx.x;   // grid = NG/256 exactly

    {   // zero g_pooled: 128K float4 over 16384 threads -> 8 each
        float4 z = make_float4(0.f, 0.f, 0.f, 0.f);
        float4* pp = (float4*)g_pooled;
#pragma unroll
        for (int r = 0; r < 8; r++) pp[g * 8 + r] = z;
    }

    float in5[5];
#pragma unroll
    for (int j = 0; j < 5; j++) in5[j] = g_aggr[g * 5 + j];

    u64 acc[20];
#pragma unroll
    for (int j = 0; j < 20; j++) acc[j] = 0ULL;
#pragma unroll
    for (int k = 0; k < 5; k++) {
        u64 a = pk2(in5[k], in5[k]);
#pragma unroll
        for (int q = 0; q < 20; q += 2) {
            ulonglong2 w = ldc2(&WG1[k * 20 + q]);
            acc[q]     = ffma2(a, w.x, acc[q]);
            acc[q + 1] = ffma2(a, w.y, acc[q + 1]);
        }
    }
    float hf[40];
#pragma unroll
    for (int j = 0; j < 20; j++) {
        float lo, hi; up2(acc[j], lo, hi);
        hf[2 * j] = lrelu(lo); hf[2 * j + 1] = lrelu(hi);
    }
    u64 o01 = 0ULL, o23 = 0ULL;
#pragma unroll
    for (int k = 0; k < 40; k++) {
        u64 a = pk2(hf[k], hf[k]);
        ulonglong2 w = ldc2(&WG2[k * 2]);
        o01 = ffma2(a, w.x, o01);
        o23 = ffma2(a, w.y, o23);
    }
    float o0, o1, o2, o3;
    up2(o01, o0, o1); up2(o23, o2, o3);
    float xg[4] = {lrelu(o0), lrelu(o1), lrelu(o2), lrelu(o3)};

    // hbias = W1b·xg over Wo1 rows 5..8 -> per-graph constant
    u64 hb[20];
#pragma unroll
    for (int q = 0; q < 20; q++) hb[q] = 0ULL;
#pragma unroll
    for (int k = 0; k < 4; k++) {
        u64 a = pk2(xg[k], xg[k]);
#pragma unroll
        for (int q = 0; q < 20; q += 2) {
            ulonglong2 w = ldc2(&WO1[(5 + k) * 20 + q]);
            hb[q]     = ffma2(a, w.x, hb[q]);
            hb[q + 1] = ffma2(a, w.y, hb[q + 1]);
        }
    }
#pragma unroll
    for (int q = 0; q < 10; q++)
        ((ulonglong2*)(g_hbias + g * 20))[q] = make_ulonglong2(hb[2 * q], hb[2 * q + 1]);
}

// =====================================================================
// Pass 3: xo = ffn([xe, xg], Wo1, Wo2); segment-sum -> g_pooled.  P=2.
// Layer 2 regrouped 8x4 outputs (halves live accumulators); 192-thread
// blocks x3 -> 18 warps/SM at 113-reg cap, above natural demand.
// =====================================================================
__global__ void __launch_bounds__(192, 3) k_out(const int* __restrict__ batch) {
    int tid = threadIdx.x;
    int t = blockIdx.x * 192 + tid;
    int i0 = t * 2;
    if (i0 >= NPTS) return;   // 1M threads; tail is whole warps

    int2 bb = *(const int2*)(batch + i0);
    int bA = bb.x, bB = bb.y;
    bool same = (bA == bB);

    // init hidden accumulators from per-graph bias (L2-resident LDG.128)
    u64 hA[20], hB[20];
    {
        const ulonglong2* pA = (const ulonglong2*)(g_hbias + bA * 20);
#pragma unroll
        for (int q = 0; q < 10; q++) {
            ulonglong2 v = pA[q];
            hA[2 * q] = v.x; hA[2 * q + 1] = v.y;
        }
        if (same) {
#pragma unroll
            for (int q = 0; q < 20; q++) hB[q] = hA[q];
        } else {
            const ulonglong2* pB = (const ulonglong2*)(g_hbias + bB * 20);
#pragma unroll
            for (int q = 0; q < 10; q++) {
                ulonglong2 v = pB[q];
                hB[2 * q] = v.x; hB[2 * q + 1] = v.y;
            }
        }
    }

    float inA[5], inB[5];
    {
        const float2* xep = (const float2*)(g_xe + i0 * 5);
        float2 e0 = xep[0], e1 = xep[1], e2 = xep[2], e3 = xep[3], e4 = xep[4];
        inA[0] = e0.x; inA[1] = e0.y; inA[2] = e1.x; inA[3] = e1.y; inA[4] = e2.x;
        inB[0] = e2.y; inB[1] = e3.x; inB[2] = e3.y; inB[3] = e4.x; inB[4] = e4.y;
    }

    // hidden: += W1a·xe (5 inputs only)
#pragma unroll
    for (int k = 0; k < 5; k++) {
        u64 aA = pk2(inA[k], inA[k]);
        u64 aB = pk2(inB[k], inB[k]);
#pragma unroll
        for (int q = 0; q < 20; q += 2) {
            ulonglong2 w = ldc2(&WO1[k * 20 + q]);
            hA[q]     = ffma2(aA, w.x, hA[q]);
            hA[q + 1] = ffma2(aA, w.y, hA[q + 1]);
            hB[q]     = ffma2(aB, w.x, hB[q]);
            hB[q + 1] = ffma2(aB, w.y, hB[q + 1]);
        }
    }
#pragma unroll
    for (int q = 0; q < 20; q++) { hA[q] = plrelu2(hA[q]); hB[q] = plrelu2(hB[q]); }

    // segment bookkeeping (once)
    unsigned peers = __match_any_sync(0xffffffffu, bA);
    int lane = tid & 31;
    int hiL = 31 - __clz(peers);
    bool leader = (lane == __ffs(peers) - 1);

    // out 40 -> 32: 8 groups of 4 outputs (same LDC/FFMA totals, half the
    // live accumulators vs 4x8 grouping)
#pragma unroll
    for (int grp = 0; grp < 8; grp++) {
        u64 oA[4], oB[4];
#pragma unroll
        for (int jj = 0; jj < 4; jj++) { oA[jj] = 0ULL; oB[jj] = 0ULL; }
#pragma unroll
        for (int q = 0; q < 20; q += 2) {
            u64 a0 = hA[q], a1 = hA[q + 1];
            u64 b0 = hB[q], b1 = hB[q + 1];
#pragma unroll
            for (int jj = 0; jj < 4; jj++) {
                ulonglong2 w = ldc2(&WO2T[(grp * 4 + jj) * 20 + q]);
                oA[jj] = ffma2(a0, w.x, oA[jj]);
                oA[jj] = ffma2(a1, w.y, oA[jj]);
                oB[jj] = ffma2(b0, w.x, oB[jj]);
                oB[jj] = ffma2(b1, w.y, oB[jj]);
            }
        }

        // pack channel pairs, activate packed, merge A+B, reduce packed
        u64 pvB[2], m[2];
#pragma unroll
        for (int h2 = 0; h2 < 2; h2++) {
            float l0, h0, l1, h1;
            up2(oA[2 * h2], l0, h0);
            up2(oA[2 * h2 + 1], l1, h1);
            u64 pvA = plrelu2(pk2(l0 + h0, l1 + h1));
            up2(oB[2 * h2], l0, h0);
            up2(oB[2 * h2 + 1], l1, h1);
            pvB[h2] = plrelu2(pk2(l0 + h0, l1 + h1));
            m[h2] = same ? add2(pvA, pvB[h2]) : pvA;
        }
#pragma unroll
        for (int d = 1; d < 32; d <<= 1) {
            u64 s0 = __shfl_down_sync(0xffffffffu, m[0], d);
            u64 s1 = __shfl_down_sync(0xffffffffu, m[1], d);
            if (lane + d <= hiL) { m[0] = add2(m[0], s0); m[1] = add2(m[1], s1); }
        }
        if (leader) {
#pragma unroll
            for (int h2 = 0; h2 < 2; h2++) {
                float lo, hi; up2(m[h2], lo, hi);
                atomicAdd(&g_pooled[bA * 32 + grp * 4 + 2 * h2],     lo);
                atomicAdd(&g_pooled[bA * 32 + grp * 4 + 2 * h2 + 1], hi);
            }
        }
        if (!same) {
#pragma unroll
            for (int h2 = 0; h2 < 2; h2++) {
                float lo, hi; up2(pvB[h2], lo, hi);
                atomicAdd(&g_pooled[bB * 32 + grp * 4 + 2 * h2],     lo);
                atomicAdd(&g_pooled[bB * 32 + grp * 4 + 2 * h2 + 1], hi);
            }
        }
    }
}

// =====================================================================
// Pass 4: out = ffn(pooled, Wd1, Wd2, final_linear=True)
// =====================================================================
__global__ void __launch_bounds__(256) k_disc(float* __restrict__ out) {
    int g = blockIdx.x * 256 + threadIdx.x;   // grid = NG/256 exactly
    float p[32];
#pragma unroll
    for (int j = 0; j < 32; j++) p[j] = g_pooled[g * 32 + j];

    u64 acc[20];
#pragma unroll
    for (int j = 0; j < 20; j++) acc[j] = 0ULL;
#pragma unroll
    for (int k = 0; k < 32; k++) {
        u64 a = pk2(p[k], p[k]);
#pragma unroll
        for (int q = 0; q < 20; q += 2) {
            ulonglong2 w = ldc2(&WD1[k * 20 + q]);
            acc[q]     = ffma2(a, w.x, acc[q]);
            acc[q + 1] = ffma2(a, w.y, acc[q + 1]);
        }
    }
    u64 s = 0ULL;
#pragma unroll
    for (int j = 0; j < 20; j += 2) {
        ulonglong2 w = ldc2(&WD2[j]);
        s = ffma2(plrelu2(acc[j]),     w.x, s);
        s = ffma2(plrelu2(acc[j + 1]), w.y, s);
    }
    float lo, hi; up2(s, lo, hi);
    out[g] = lo + hi;   // final_linear: no activation
}

extern "C" void kernel_launch(void* const* d_in, const int* in_sizes, int n_in,
                              void* d_out, int out_size) {
    const float* x     = (const float*)d_in[0];
    const int*   batch = (const int*)d_in[1];
    float* out = (float*)d_out;

    // Build the full weight image + zero g_aggr, then ONE constant upload
    k_pre<<<80, 256>>>((const float*)d_in[2], (const float*)d_in[3],
                       (const float*)d_in[4], (const float*)d_in[5],
                       (const float*)d_in[6], (const float*)d_in[7],
                       (const float*)d_in[8], (const float*)d_in[9]);
    void* pStage = nullptr;
    cudaGetSymbolAddress(&pStage, g_stage);
    cudaMemcpyToSymbolAsync(cAll, pStage, 1820 * 8, 0, cudaMemcpyDeviceToDevice, 0);

    const int nblk2 = (NPTS / 2 + 255) / 256;   // k_emb: 256-thread blocks
    const int nblk3 = (NPTS / 2 + 191) / 192;   // k_out: 192-thread blocks
    k_emb<<<nblk2, 256>>>(x, batch);
    k_glob<<<NG / 256, 256>>>();
    k_out<<<nblk3, 192>>>(batch);
    k_disc<<<NG / 256, 256>>>(out);
}

// round 14
// speedup vs baseline: 1.0872x; 1.0872x over previous
#include <cuda_runtime.h>

#define NPTS 2000000
#define NG   16384

typedef unsigned long long u64;

// Scratch (device globals: allocation-free, graph-capturable)
__device__ float g_xe[NPTS * 5];        // per-point embedding
__device__ float g_aggr[NG * 5];        // segment sum of xe
__device__ float g_pooled[NG * 32];     // segment sum of xo
__device__ u64   g_hbias[NG * 20];      // per-graph W1b·xg, packed pairs
__device__ u64   g_stage[1820];         // staging image for the constant bank

// One constant bank; regions 16B-aligned
__constant__ __align__(16) u64 cAll[1820];
#define WE1  (cAll + 0)      // [3][40] packed over outputs            (60)
#define WE2T (cAll + 60)     // transposed: [5 outputs][20 pairs]      (100)
#define WG1  (cAll + 160)    // [5][40]                                (100)
#define WG2  (cAll + 260)    // [40][4]                                (80)
#define WO1  (cAll + 340)    // [9][40]: rows 0-4 k_out, 5-8 k_glob    (180)
#define WO2T (cAll + 520)    // transposed: [32 outputs][20 pairs]     (640)
#define WD1  (cAll + 1160)   // [32][40]                               (640)
#define WD2  (cAll + 1800)   // [40][1]                                (20)

// ---------- packed f32x2 helpers ----------
__device__ __forceinline__ u64 pk2(float lo, float hi) {
    u64 r; asm("mov.b64 %0, {%1, %2};" : "=l"(r) : "f"(lo), "f"(hi)); return r;
}
__device__ __forceinline__ void up2(u64 v, float& lo, float& hi) {
    asm("mov.b64 {%0, %1}, %2;" : "=f"(lo), "=f"(hi) : "l"(v));
}
__device__ __forceinline__ u64 ffma2(u64 a, u64 b, u64 c) {
    u64 d; asm("fma.rn.f32x2 %0, %1, %2, %3;" : "=l"(d) : "l"(a), "l"(b), "l"(c)); return d;
}
__device__ __forceinline__ u64 mul2(u64 a, u64 b) {
    u64 d; asm("mul.rn.f32x2 %0, %1, %2;" : "=l"(d) : "l"(a), "l"(b)); return d;
}
__device__ __forceinline__ u64 add2(u64 a, u64 b) {
    u64 d; asm("add.rn.f32x2 %0, %1, %2;" : "=l"(d) : "l"(a), "l"(b)); return d;
}
// scalar leaky_relu (exact)
__device__ __forceinline__ float lrelu(float v) { return fmaxf(v, 0.01f * v); }
// packed leaky_relu: 0.505x + 0.495|x| (== lrelu to ~6e-6 rel)
__device__ __forceinline__ u64 plrelu2(u64 v) {
    u64 cA = pk2(0.505f, 0.505f), cB = pk2(0.495f, 0.495f);
    u64 av = v & 0x7FFFFFFF7FFFFFFFULL;
    return ffma2(av, cB, mul2(v, cA));
}
// 16B constant load helper
__device__ __forceinline__ ulonglong2 ldc2(const u64* p) {
    return *(const ulonglong2*)p;
}

// ---------- pre: zero g_aggr + build full weight image in g_stage ----------
__global__ void __launch_bounds__(256) k_pre(const float* __restrict__ We1,
                                             const float* __restrict__ We2,
                                             const float* __restrict__ Wg1,
                                             const float* __restrict__ Wg2,
                                             const float* __restrict__ Wo1,
                                             const float* __restrict__ Wo2,
                                             const float* __restrict__ Wd1,
                                             const float* __restrict__ Wd2) {
    int i = blockIdx.x * 256 + threadIdx.x;
    if (i < NG * 5 / 4) ((float4*)g_aggr)[i] = make_float4(0.f, 0.f, 0.f, 0.f);
    if (i < 1820) {
        u64 v;
        if (i < 60)        v = ((const u64*)We1)[i];
        else if (i < 160)  { int t = i - 60;  int j = t / 20, q = t % 20;
                             v = pk2(We2[(2 * q) * 5 + j], We2[(2 * q + 1) * 5 + j]); }
        else if (i < 260)  v = ((const u64*)Wg1)[i - 160];
        else if (i < 340)  v = ((const u64*)Wg2)[i - 260];
        else if (i < 520)  v = ((const u64*)Wo1)[i - 340];
        else if (i < 1160) { int t = i - 520; int j = t / 20, q = t % 20;
                             v = pk2(Wo2[(2 * q) * 32 + j], Wo2[(2 * q + 1) * 32 + j]); }
        else if (i < 1800) v = ((const u64*)Wd1)[i - 1160];
        else               v = ((const u64*)Wd2)[i - 1800];
        g_stage[i] = v;
    }
}

// =====================================================================
// Pass 1: xe = ffn(x, We1, We2); store xe; segment-sum -> g_aggr.  P=2.
// =====================================================================
__global__ void __launch_bounds__(256, 2) k_emb(const float* __restrict__ x,
                                                const int* __restrict__ batch) {
    int tid = threadIdx.x;
    int t = blockIdx.x * 256 + tid;
    int i0 = t * 2;
    if (i0 >= NPTS) return;   // NPTS % 64 == 0 -> surviving warps are full

    const float2* xp = (const float2*)(x + i0 * 3);
    float2 p0 = xp[0], p1 = xp[1], p2 = xp[2];
    float inA[3] = {p0.x, p0.y, p1.x};
    float inB[3] = {p1.y, p2.x, p2.y};

    // hidden 3 -> 40 (packed over outputs)
    u64 hA[20], hB[20];
#pragma unroll
    for (int q = 0; q < 20; q++) { hA[q] = 0ULL; hB[q] = 0ULL; }
#pragma unroll
    for (int k = 0; k < 3; k++) {
        u64 aA = pk2(inA[k], inA[k]);
        u64 aB = pk2(inB[k], inB[k]);
#pragma unroll
        for (int q = 0; q < 20; q += 2) {
            ulonglong2 w = ldc2(&WE1[k * 20 + q]);
            hA[q]     = ffma2(aA, w.x, hA[q]);
            hA[q + 1] = ffma2(aA, w.y, hA[q + 1]);
            hB[q]     = ffma2(aB, w.x, hB[q]);
            hB[q + 1] = ffma2(aB, w.y, hB[q + 1]);
        }
    }
#pragma unroll
    for (int q = 0; q < 20; q++) { hA[q] = plrelu2(hA[q]); hB[q] = plrelu2(hB[q]); }

    // out 40 -> 5: packed dot over hidden pairs (transposed weights)
    float xeA[5], xeB[5];
#pragma unroll
    for (int j = 0; j < 5; j++) {
        u64 aA = 0ULL, aB = 0ULL;
#pragma unroll
        for (int q = 0; q < 20; q += 2) {
            ulonglong2 w = ldc2(&WE2T[j * 20 + q]);
            aA = ffma2(hA[q], w.x, aA); aA = ffma2(hA[q + 1], w.y, aA);
            aB = ffma2(hB[q], w.x, aB); aB = ffma2(hB[q + 1], w.y, aB);
        }
        float lo, hi;
        up2(aA, lo, hi); xeA[j] = lrelu(lo + hi);
        up2(aB, lo, hi); xeB[j] = lrelu(lo + hi);
    }

    // store xe for both points: 10 consecutive floats -> 5 STG.64
    {
        float2* xo = (float2*)(g_xe + i0 * 5);
        xo[0] = make_float2(xeA[0], xeA[1]);
        xo[1] = make_float2(xeA[2], xeA[3]);
        xo[2] = make_float2(xeA[4], xeB[0]);
        xo[3] = make_float2(xeB[1], xeB[2]);
        xo[4] = make_float2(xeB[3], xeB[4]);
    }

    // segmented sum -> g_aggr (channels (0,1),(2,3) packed, 4 scalar)
    int2 bb = *(const int2*)(batch + i0);
    int bA = bb.x, bB = bb.y;
    bool same = (bA == bB);
    unsigned peers = __match_any_sync(0xffffffffu, bA);
    int lane = tid & 31;
    int hiL = 31 - __clz(peers);
    bool leader = (lane == __ffs(peers) - 1);
    // hoisted guard predicates (loop-invariant)
    bool pd[5];
#pragma unroll
    for (int s = 0; s < 5; s++) pd[s] = (lane + (1 << s)) <= hiL;

    u64 m01 = pk2(xeA[0], xeA[1]);
    u64 m23 = pk2(xeA[2], xeA[3]);
    float m4 = xeA[4];
    if (same) {
        m01 = add2(m01, pk2(xeB[0], xeB[1]));
        m23 = add2(m23, pk2(xeB[2], xeB[3]));
        m4 += xeB[4];
    }
#pragma unroll
    for (int s = 0; s < 5; s++) {
        int d = 1 << s;
        u64 s0 = __shfl_down_sync(0xffffffffu, m01, d);
        u64 s1 = __shfl_down_sync(0xffffffffu, m23, d);
        float s2 = __shfl_down_sync(0xffffffffu, m4, d);
        if (pd[s]) { m01 = add2(m01, s0); m23 = add2(m23, s1); m4 += s2; }
    }
    if (leader) {
        float a0, a1; up2(m01, a0, a1);
        float a2, a3; up2(m23, a2, a3);
        atomicAdd(&g_aggr[bA * 5 + 0], a0);
        atomicAdd(&g_aggr[bA * 5 + 1], a1);
        atomicAdd(&g_aggr[bA * 5 + 2], a2);
        atomicAdd(&g_aggr[bA * 5 + 3], a3);
        atomicAdd(&g_aggr[bA * 5 + 4], m4);
    }
    if (!same) {
#pragma unroll
        for (int c = 0; c < 5; c++) atomicAdd(&g_aggr[bB * 5 + c], xeB[c]);
    }
}

// =====================================================================
// Pass 2: xg = ffn(x_aggr, Wg1, Wg2); hbias = W1b·xg -> g_hbias.
// Also zeroes g_pooled.
// =====================================================================
__global__ void __launch_bounds__(256) k_glob() {
    int g = blockIdx.x * 256 + threadIdx.x;   // grid = NG/256 exactly

    {   // zero g_pooled: 128K float4 over 16384 threads -> 8 each
        float4 z = make_float4(0.f, 0.f, 0.f, 0.f);
        float4* pp = (float4*)g_pooled;
#pragma unroll
        for (int r = 0; r < 8; r++) pp[g * 8 + r] = z;
    }

    float in5[5];
#pragma unroll
    for (int j = 0; j < 5; j++) in5[j] = g_aggr[g * 5 + j];

    u64 acc[20];
#pragma unroll
    for (int j = 0; j < 20; j++) acc[j] = 0ULL;
#pragma unroll
    for (int k = 0; k < 5; k++) {
        u64 a = pk2(in5[k], in5[k]);
#pragma unroll
        for (int q = 0; q < 20; q += 2) {
            ulonglong2 w = ldc2(&WG1[k * 20 + q]);
            acc[q]     = ffma2(a, w.x, acc[q]);
            acc[q + 1] = ffma2(a, w.y, acc[q + 1]);
        }
    }
    float hf[40];
#pragma unroll
    for (int j = 0; j < 20; j++) {
        float lo, hi; up2(acc[j], lo, hi);
        hf[2 * j] = lrelu(lo); hf[2 * j + 1] = lrelu(hi);
    }
    u64 o01 = 0ULL, o23 = 0ULL;
#pragma unroll
    for (int k = 0; k < 40; k++) {
        u64 a = pk2(hf[k], hf[k]);
        ulonglong2 w = ldc2(&WG2[k * 2]);
        o01 = ffma2(a, w.x, o01);
        o23 = ffma2(a, w.y, o23);
    }
    float o0, o1, o2, o3;
    up2(o01, o0, o1); up2(o23, o2, o3);
    float xg[4] = {lrelu(o0), lrelu(o1), lrelu(o2), lrelu(o3)};

    // hbias = W1b·xg over Wo1 rows 5..8 -> per-graph constant
    u64 hb[20];
#pragma unroll
    for (int q = 0; q < 20; q++) hb[q] = 0ULL;
#pragma unroll
    for (int k = 0; k < 4; k++) {
        u64 a = pk2(xg[k], xg[k]);
#pragma unroll
        for (int q = 0; q < 20; q += 2) {
            ulonglong2 w = ldc2(&WO1[(5 + k) * 20 + q]);
            hb[q]     = ffma2(a, w.x, hb[q]);
            hb[q + 1] = ffma2(a, w.y, hb[q + 1]);
        }
    }
#pragma unroll
    for (int q = 0; q < 10; q++)
        ((ulonglong2*)(g_hbias + g * 20))[q] = make_ulonglong2(hb[2 * q], hb[2 * q + 1]);
}

// =====================================================================
// Pass 3: xo = ffn([xe, xg], Wo1, Wo2); segment-sum -> g_pooled.  P=2.
// (R12/R9 structure: both h arrays in regs, 128-reg cap, packed epilogue.)
// =====================================================================
__global__ void __launch_bounds__(256, 2) k_out(const int* __restrict__ batch) {
    int tid = threadIdx.x;
    int t = blockIdx.x * 256 + tid;
    int i0 = t * 2;
    if (i0 >= NPTS) return;

    int2 bb = *(const int2*)(batch + i0);
    int bA = bb.x, bB = bb.y;
    bool same = (bA == bB);

    // init hidden accumulators from per-graph bias (L2-resident LDG.128)
    u64 hA[20], hB[20];
    {
        const ulonglong2* pA = (const ulonglong2*)(g_hbias + bA * 20);
#pragma unroll
        for (int q = 0; q < 10; q++) {
            ulonglong2 v = pA[q];
            hA[2 * q] = v.x; hA[2 * q + 1] = v.y;
        }
        if (same) {
#pragma unroll
            for (int q = 0; q < 20; q++) hB[q] = hA[q];
        } else {
            const ulonglong2* pB = (const ulonglong2*)(g_hbias + bB * 20);
#pragma unroll
            for (int q = 0; q < 10; q++) {
                ulonglong2 v = pB[q];
                hB[2 * q] = v.x; hB[2 * q + 1] = v.y;
            }
        }
    }

    float inA[5], inB[5];
    {
        const float2* xep = (const float2*)(g_xe + i0 * 5);
        float2 e0 = xep[0], e1 = xep[1], e2 = xep[2], e3 = xep[3], e4 = xep[4];
        inA[0] = e0.x; inA[1] = e0.y; inA[2] = e1.x; inA[3] = e1.y; inA[4] = e2.x;
        inB[0] = e2.y; inB[1] = e3.x; inB[2] = e3.y; inB[3] = e4.x; inB[4] = e4.y;
    }

    // hidden: += W1a·xe (5 inputs only)
#pragma unroll
    for (int k = 0; k < 5; k++) {
        u64 aA = pk2(inA[k], inA[k]);
        u64 aB = pk2(inB[k], inB[k]);
#pragma unroll
        for (int q = 0; q < 20; q += 2) {
            ulonglong2 w = ldc2(&WO1[k * 20 + q]);
            hA[q]     = ffma2(aA, w.x, hA[q]);
            hA[q + 1] = ffma2(aA, w.y, hA[q + 1]);
            hB[q]     = ffma2(aB, w.x, hB[q]);
            hB[q + 1] = ffma2(aB, w.y, hB[q + 1]);
        }
    }
#pragma unroll
    for (int q = 0; q < 20; q++) { hA[q] = plrelu2(hA[q]); hB[q] = plrelu2(hB[q]); }

    // segment bookkeeping (once); hoisted guard predicates
    unsigned peers = __match_any_sync(0xffffffffu, bA);
    int lane = tid & 31;
    int hiL = 31 - __clz(peers);
    bool leader = (lane == __ffs(peers) - 1);
    bool pd[5];
#pragma unroll
    for (int s = 0; s < 5; s++) pd[s] = (lane + (1 << s)) <= hiL;

    // out 40 -> 32: 4 groups of 8 outputs
#pragma unroll
    for (int grp = 0; grp < 4; grp++) {
        u64 oA[8], oB[8];
#pragma unroll
        for (int jj = 0; jj < 8; jj++) { oA[jj] = 0ULL; oB[jj] = 0ULL; }
#pragma unroll
        for (int q = 0; q < 20; q += 2) {
            u64 a0 = hA[q], a1 = hA[q + 1];
            u64 b0 = hB[q], b1 = hB[q + 1];
#pragma unroll
            for (int jj = 0; jj < 8; jj++) {
                ulonglong2 w = ldc2(&WO2T[(grp * 8 + jj) * 20 + q]);
                oA[jj] = ffma2(a0, w.x, oA[jj]);
                oA[jj] = ffma2(a1, w.y, oA[jj]);
                oB[jj] = ffma2(b0, w.x, oB[jj]);
                oB[jj] = ffma2(b1, w.y, oB[jj]);
            }
        }

        // pack channel pairs, activate packed, merge A+B, reduce packed
        u64 pvB[4], m[4];
#pragma unroll
        for (int h2 = 0; h2 < 4; h2++) {
            float l0, h0, l1, h1;
            up2(oA[2 * h2], l0, h0);
            up2(oA[2 * h2 + 1], l1, h1);
            u64 pvA = plrelu2(pk2(l0 + h0, l1 + h1));
            up2(oB[2 * h2], l0, h0);
            up2(oB[2 * h2 + 1], l1, h1);
            pvB[h2] = plrelu2(pk2(l0 + h0, l1 + h1));
            m[h2] = same ? add2(pvA, pvB[h2]) : pvA;
        }
#pragma unroll
        for (int h2 = 0; h2 < 4; h2++) {
            u64 v = m[h2];
#pragma unroll
            for (int s = 0; s < 5; s++) {
                u64 sv = __shfl_down_sync(0xffffffffu, v, 1 << s);
                if (pd[s]) v = add2(v, sv);
            }
            m[h2] = v;
        }
        if (leader) {
#pragma unroll
            for (int h2 = 0; h2 < 4; h2++) {
                float lo, hi; up2(m[h2], lo, hi);
                atomicAdd(&g_pooled[bA * 32 + grp * 8 + 2 * h2],     lo);
                atomicAdd(&g_pooled[bA * 32 + grp * 8 + 2 * h2 + 1], hi);
            }
        }
        if (!same) {
#pragma unroll
            for (int h2 = 0; h2 < 4; h2++) {
                float lo, hi; up2(pvB[h2], lo, hi);
                atomicAdd(&g_pooled[bB * 32 + grp * 8 + 2 * h2],     lo);
                atomicAdd(&g_pooled[bB * 32 + grp * 8 + 2 * h2 + 1], hi);
            }
        }
    }
}

// =====================================================================
// Pass 4: out = ffn(pooled, Wd1, Wd2, final_linear=True)
// =====================================================================
__global__ void __launch_bounds__(256) k_disc(float* __restrict__ out) {
    int g = blockIdx.x * 256 + threadIdx.x;   // grid = NG/256 exactly
    float p[32];
#pragma unroll
    for (int j = 0; j < 32; j++) p[j] = g_pooled[g * 32 + j];

    u64 acc[20];
#pragma unroll
    for (int j = 0; j < 20; j++) acc[j] = 0ULL;
#pragma unroll
    for (int k = 0; k < 32; k++) {
        u64 a = pk2(p[k], p[k]);
#pragma unroll
        for (int q = 0; q < 20; q += 2) {
            ulonglong2 w = ldc2(&WD1[k * 20 + q]);
            acc[q]     = ffma2(a, w.x, acc[q]);
            acc[q + 1] = ffma2(a, w.y, acc[q + 1]);
        }
    }
    u64 s = 0ULL;
#pragma unroll
    for (int j = 0; j < 20; j += 2) {
        ulonglong2 w = ldc2(&WD2[j]);
        s = ffma2(plrelu2(acc[j]),     w.x, s);
        s = ffma2(plrelu2(acc[j + 1]), w.y, s);
    }
    float lo, hi; up2(s, lo, hi);
    out[g] = lo + hi;   // final_linear: no activation
}

extern "C" void kernel_launch(void* const* d_in, const int* in_sizes, int n_in,
                              void* d_out, int out_size) {
    const float* x     = (const float*)d_in[0];
    const int*   batch = (const int*)d_in[1];
    float* out = (float*)d_out;

    // Build the full weight image + zero g_aggr, then ONE constant upload
    k_pre<<<80, 256>>>((const float*)d_in[2], (const float*)d_in[3],
                       (const float*)d_in[4], (const float*)d_in[5],
                       (const float*)d_in[6], (const float*)d_in[7],
                       (const float*)d_in[8], (const float*)d_in[9]);
    void* pStage = nullptr;
    cudaGetSymbolAddress(&pStage, g_stage);
    cudaMemcpyToSymbolAsync(cAll, pStage, 1820 * 8, 0, cudaMemcpyDeviceToDevice, 0);

    const int nblk2 = (NPTS / 2 + 255) / 256;   // P=2 kernels
    k_emb<<<nblk2, 256>>>(x, batch);
    k_glob<<<NG / 256, 256>>>();
    k_out<<<nblk2, 256>>>(batch);
    k_disc<<<NG / 256, 256>>>(out);
}

// round 16
// speedup vs baseline: 1.1005x; 1.0122x over previous
#include <cuda_runtime.h>

#define NPTS 2000000
#define NG   16384

typedef unsigned long long u64;

// Scratch (device globals: allocation-free, graph-capturable)
__device__ float g_xe[NPTS * 5];        // per-point embedding
__device__ float g_aggr[NG * 5];        // segment sum of xe
__device__ float g_pooled[NG * 32];     // segment sum of xo
__device__ u64   g_hbias[NG * 20];      // per-graph W1b·xg, packed pairs
__device__ u64   g_stage[1820];         // staging image for the constant bank

// One constant bank; regions 16B-aligned
__constant__ __align__(16) u64 cAll[1820];
#define WE1  (cAll + 0)      // [3][40] packed over outputs            (60)
#define WE2T (cAll + 60)     // transposed: [5 outputs][20 pairs]      (100)
#define WG1  (cAll + 160)    // [5][40]                                (100)
#define WG2  (cAll + 260)    // [40][4]                                (80)
#define WO1  (cAll + 340)    // [9][40]: rows 0-4 k_out, 5-8 k_glob    (180)
#define WO2T (cAll + 520)    // transposed: [32 outputs][20 pairs]     (640)
#define WD1  (cAll + 1160)   // [32][40]                               (640)
#define WD2  (cAll + 1800)   // [40][1]                                (20)

// ---------- packed f32x2 helpers ----------
__device__ __forceinline__ u64 pk2(float lo, float hi) {
    u64 r; asm("mov.b64 %0, {%1, %2};" : "=l"(r) : "f"(lo), "f"(hi)); return r;
}
__device__ __forceinline__ void up2(u64 v, float& lo, float& hi) {
    asm("mov.b64 {%0, %1}, %2;" : "=f"(lo), "=f"(hi) : "l"(v));
}
__device__ __forceinline__ u64 ffma2(u64 a, u64 b, u64 c) {
    u64 d; asm("fma.rn.f32x2 %0, %1, %2, %3;" : "=l"(d) : "l"(a), "l"(b), "l"(c)); return d;
}
__device__ __forceinline__ u64 mul2(u64 a, u64 b) {
    u64 d; asm("mul.rn.f32x2 %0, %1, %2;" : "=l"(d) : "l"(a), "l"(b)); return d;
}
__device__ __forceinline__ u64 add2(u64 a, u64 b) {
    u64 d; asm("add.rn.f32x2 %0, %1, %2;" : "=l"(d) : "l"(a), "l"(b)); return d;
}
// scalar leaky_relu (exact)
__device__ __forceinline__ float lrelu(float v) { return fmaxf(v, 0.01f * v); }
// packed leaky_relu: 0.505x + 0.495|x| (== lrelu to ~6e-6 rel)
__device__ __forceinline__ u64 plrelu2(u64 v) {
    u64 cA = pk2(0.505f, 0.505f), cB = pk2(0.495f, 0.495f);
    u64 av = v & 0x7FFFFFFF7FFFFFFFULL;
    return ffma2(av, cB, mul2(v, cA));
}
// 16B constant load helper
__device__ __forceinline__ ulonglong2 ldc2(const u64* p) {
    return *(const ulonglong2*)p;
}
// vectorized fire-and-forget atomic add (sm_90+ PTX, 8B-aligned address)
__device__ __forceinline__ void red2(float* addr, float a, float b) {
    asm volatile("red.global.add.v2.f32 [%0], {%1, %2};"
                 :: "l"(addr), "f"(a), "f"(b) : "memory");
}

// ---------- pre: zero g_aggr + build full weight image in g_stage ----------
__global__ void __launch_bounds__(256) k_pre(const float* __restrict__ We1,
                                             const float* __restrict__ We2,
                                             const float* __restrict__ Wg1,
                                             const float* __restrict__ Wg2,
                                             const float* __restrict__ Wo1,
                                             const float* __restrict__ Wo2,
                                             const float* __restrict__ Wd1,
                                             const float* __restrict__ Wd2) {
    int i = blockIdx.x * 256 + threadIdx.x;
    if (i < NG * 5 / 4) ((float4*)g_aggr)[i] = make_float4(0.f, 0.f, 0.f, 0.f);
    if (i < 1820) {
        u64 v;
        if (i < 60)        v = ((const u64*)We1)[i];
        else if (i < 160)  { int t = i - 60;  int j = t / 20, q = t % 20;
                             v = pk2(We2[(2 * q) * 5 + j], We2[(2 * q + 1) * 5 + j]); }
        else if (i < 260)  v = ((const u64*)Wg1)[i - 160];
        else if (i < 340)  v = ((const u64*)Wg2)[i - 260];
        else if (i < 520)  v = ((const u64*)Wo1)[i - 340];
        else if (i < 1160) { int t = i - 520; int j = t / 20, q = t % 20;
                             v = pk2(Wo2[(2 * q) * 32 + j], Wo2[(2 * q + 1) * 32 + j]); }
        else if (i < 1800) v = ((const u64*)Wd1)[i - 1160];
        else               v = ((const u64*)Wd2)[i - 1800];
        g_stage[i] = v;
    }
}

// =====================================================================
// Pass 1: xe = ffn(x, We1, We2); store xe; segment-sum -> g_aggr.  P=2.
// =====================================================================
__global__ void __launch_bounds__(256, 2) k_emb(const float* __restrict__ x,
                                                const int* __restrict__ batch) {
    int tid = threadIdx.x;
    int t = blockIdx.x * 256 + tid;
    int i0 = t * 2;
    if (i0 >= NPTS) return;   // NPTS % 64 == 0 -> surviving warps are full

    const float2* xp = (const float2*)(x + i0 * 3);
    float2 p0 = xp[0], p1 = xp[1], p2 = xp[2];
    float inA[3] = {p0.x, p0.y, p1.x};
    float inB[3] = {p1.y, p2.x, p2.y};

    // hidden 3 -> 40 (packed over outputs)
    u64 hA[20], hB[20];
#pragma unroll
    for (int q = 0; q < 20; q++) { hA[q] = 0ULL; hB[q] = 0ULL; }
#pragma unroll
    for (int k = 0; k < 3; k++) {
        u64 aA = pk2(inA[k], inA[k]);
        u64 aB = pk2(inB[k], inB[k]);
#pragma unroll
        for (int q = 0; q < 20; q += 2) {
            ulonglong2 w = ldc2(&WE1[k * 20 + q]);
            hA[q]     = ffma2(aA, w.x, hA[q]);
            hA[q + 1] = ffma2(aA, w.y, hA[q + 1]);
            hB[q]     = ffma2(aB, w.x, hB[q]);
            hB[q + 1] = ffma2(aB, w.y, hB[q + 1]);
        }
    }
#pragma unroll
    for (int q = 0; q < 20; q++) { hA[q] = plrelu2(hA[q]); hB[q] = plrelu2(hB[q]); }

    // out 40 -> 5: packed dot over hidden pairs (transposed weights)
    float xeA[5], xeB[5];
#pragma unroll
    for (int j = 0; j < 5; j++) {
        u64 aA = 0ULL, aB = 0ULL;
#pragma unroll
        for (int q = 0; q < 20; q += 2) {
            ulonglong2 w = ldc2(&WE2T[j * 20 + q]);
            aA = ffma2(hA[q], w.x, aA); aA = ffma2(hA[q + 1], w.y, aA);
            aB = ffma2(hB[q], w.x, aB); aB = ffma2(hB[q + 1], w.y, aB);
        }
        float lo, hi;
        up2(aA, lo, hi); xeA[j] = lrelu(lo + hi);
        up2(aB, lo, hi); xeB[j] = lrelu(lo + hi);
    }

    // store xe for both points: 10 consecutive floats -> 5 STG.64
    {
        float2* xo = (float2*)(g_xe + i0 * 5);
        xo[0] = make_float2(xeA[0], xeA[1]);
        xo[1] = make_float2(xeA[2], xeA[3]);
        xo[2] = make_float2(xeA[4], xeB[0]);
        xo[3] = make_float2(xeB[1], xeB[2]);
        xo[4] = make_float2(xeB[3], xeB[4]);
    }

    // segmented sum -> g_aggr (channels (0,1),(2,3) packed, 4 scalar)
    int2 bb = *(const int2*)(batch + i0);
    int bA = bb.x, bB = bb.y;
    bool same = (bA == bB);
    unsigned peers = __match_any_sync(0xffffffffu, bA);
    int lane = tid & 31;
    int hiL = 31 - __clz(peers);
    bool leader = (lane == __ffs(peers) - 1);
    bool pd[5];
#pragma unroll
    for (int s = 0; s < 5; s++) pd[s] = (lane + (1 << s)) <= hiL;

    u64 m01 = pk2(xeA[0], xeA[1]);
    u64 m23 = pk2(xeA[2], xeA[3]);
    float m4 = xeA[4];
    if (same) {
        m01 = add2(m01, pk2(xeB[0], xeB[1]));
        m23 = add2(m23, pk2(xeB[2], xeB[3]));
        m4 += xeB[4];
    }
#pragma unroll
    for (int s = 0; s < 5; s++) {
        int d = 1 << s;
        u64 s0 = __shfl_down_sync(0xffffffffu, m01, d);
        u64 s1 = __shfl_down_sync(0xffffffffu, m23, d);
        float s2 = __shfl_down_sync(0xffffffffu, m4, d);
        if (pd[s]) { m01 = add2(m01, s0); m23 = add2(m23, s1); m4 += s2; }
    }
    if (leader) {
        float a0, a1; up2(m01, a0, a1);
        float a2, a3; up2(m23, a2, a3);
        atomicAdd(&g_aggr[bA * 5 + 0], a0);
        atomicAdd(&g_aggr[bA * 5 + 1], a1);
        atomicAdd(&g_aggr[bA * 5 + 2], a2);
        atomicAdd(&g_aggr[bA * 5 + 3], a3);
        atomicAdd(&g_aggr[bA * 5 + 4], m4);
    }
    if (!same) {
#pragma unroll
        for (int c = 0; c < 5; c++) atomicAdd(&g_aggr[bB * 5 + c], xeB[c]);
    }
}

// =====================================================================
// Pass 2: xg = ffn(x_aggr, Wg1, Wg2); hbias = W1b·xg -> g_hbias.
// Also zeroes g_pooled.
// =====================================================================
__global__ void __launch_bounds__(256) k_glob() {
    int g = blockIdx.x * 256 + threadIdx.x;   // grid = NG/256 exactly

    {   // zero g_pooled: 128K float4 over 16384 threads -> 8 each
        float4 z = make_float4(0.f, 0.f, 0.f, 0.f);
        float4* pp = (float4*)g_pooled;
#pragma unroll
        for (int r = 0; r < 8; r++) pp[g * 8 + r] = z;
    }

    float in5[5];
#pragma unroll
    for (int j = 0; j < 5; j++) in5[j] = g_aggr[g * 5 + j];

    u64 acc[20];
#pragma unroll
    for (int j = 0; j < 20; j++) acc[j] = 0ULL;
#pragma unroll
    for (int k = 0; k < 5; k++) {
        u64 a = pk2(in5[k], in5[k]);
#pragma unroll
        for (int q = 0; q < 20; q += 2) {
            ulonglong2 w = ldc2(&WG1[k * 20 + q]);
            acc[q]     = ffma2(a, w.x, acc[q]);
            acc[q + 1] = ffma2(a, w.y, acc[q + 1]);
        }
    }
    float hf[40];
#pragma unroll
    for (int j = 0; j < 20; j++) {
        float lo, hi; up2(acc[j], lo, hi);
        hf[2 * j] = lrelu(lo); hf[2 * j + 1] = lrelu(hi);
    }
    u64 o01 = 0ULL, o23 = 0ULL;
#pragma unroll
    for (int k = 0; k < 40; k++) {
        u64 a = pk2(hf[k], hf[k]);
        ulonglong2 w = ldc2(&WG2[k * 2]);
        o01 = ffma2(a, w.x, o01);
        o23 = ffma2(a, w.y, o23);
    }
    float o0, o1, o2, o3;
    up2(o01, o0, o1); up2(o23, o2, o3);
    float xg[4] = {lrelu(o0), lrelu(o1), lrelu(o2), lrelu(o3)};

    // hbias = W1b·xg over Wo1 rows 5..8 -> per-graph constant
    u64 hb[20];
#pragma unroll
    for (int q = 0; q < 20; q++) hb[q] = 0ULL;
#pragma unroll
    for (int k = 0; k < 4; k++) {
        u64 a = pk2(xg[k], xg[k]);
#pragma unroll
        for (int q = 0; q < 20; q += 2) {
            ulonglong2 w = ldc2(&WO1[(5 + k) * 20 + q]);
            hb[q]     = ffma2(a, w.x, hb[q]);
            hb[q + 1] = ffma2(a, w.y, hb[q + 1]);
        }
    }
#pragma unroll
    for (int q = 0; q < 10; q++)
        ((ulonglong2*)(g_hbias + g * 20))[q] = make_ulonglong2(hb[2 * q], hb[2 * q + 1]);
}

// =====================================================================
// Pass 3: xo = ffn([xe, xg], Wo1, Wo2); segment-sum -> g_pooled.  P=2.
// (R14 structure; leader atomics vectorized via red.global.add.v2.f32.)
// =====================================================================
__global__ void __launch_bounds__(256, 2) k_out(const int* __restrict__ batch) {
    int tid = threadIdx.x;
    int t = blockIdx.x * 256 + tid;
    int i0 = t * 2;
    if (i0 >= NPTS) return;

    int2 bb = *(const int2*)(batch + i0);
    int bA = bb.x, bB = bb.y;
    bool same = (bA == bB);

    // init hidden accumulators from per-graph bias (L2-resident LDG.128)
    u64 hA[20], hB[20];
    {
        const ulonglong2* pA = (const ulonglong2*)(g_hbias + bA * 20);
#pragma unroll
        for (int q = 0; q < 10; q++) {
            ulonglong2 v = pA[q];
            hA[2 * q] = v.x; hA[2 * q + 1] = v.y;
        }
        if (same) {
#pragma unroll
            for (int q = 0; q < 20; q++) hB[q] = hA[q];
        } else {
            const ulonglong2* pB = (const ulonglong2*)(g_hbias + bB * 20);
#pragma unroll
            for (int q = 0; q < 10; q++) {
                ulonglong2 v = pB[q];
                hB[2 * q] = v.x; hB[2 * q + 1] = v.y;
            }
        }
    }

    float inA[5], inB[5];
    {
        const float2* xep = (const float2*)(g_xe + i0 * 5);
        float2 e0 = xep[0], e1 = xep[1], e2 = xep[2], e3 = xep[3], e4 = xep[4];
        inA[0] = e0.x; inA[1] = e0.y; inA[2] = e1.x; inA[3] = e1.y; inA[4] = e2.x;
        inB[0] = e2.y; inB[1] = e3.x; inB[2] = e3.y; inB[3] = e4.x; inB[4] = e4.y;
    }

    // hidden: += W1a·xe (5 inputs only)
#pragma unroll
    for (int k = 0; k < 5; k++) {
        u64 aA = pk2(inA[k], inA[k]);
        u64 aB = pk2(inB[k], inB[k]);
#pragma unroll
        for (int q = 0; q < 20; q += 2) {
            ulonglong2 w = ldc2(&WO1[k * 20 + q]);
            hA[q]     = ffma2(aA, w.x, hA[q]);
            hA[q + 1] = ffma2(aA, w.y, hA[q + 1]);
            hB[q]     = ffma2(aB, w.x, hB[q]);
            hB[q + 1] = ffma2(aB, w.y, hB[q + 1]);
        }
    }
#pragma unroll
    for (int q = 0; q < 20; q++) { hA[q] = plrelu2(hA[q]); hB[q] = plrelu2(hB[q]); }

    // segment bookkeeping (once); hoisted guard predicates
    unsigned peers = __match_any_sync(0xffffffffu, bA);
    int lane = tid & 31;
    int hiL = 31 - __clz(peers);
    bool leader = (lane == __ffs(peers) - 1);
    bool pd[5];
#pragma unroll
    for (int s = 0; s < 5; s++) pd[s] = (lane + (1 << s)) <= hiL;

    // out 40 -> 32: 4 groups of 8 outputs
#pragma unroll
    for (int grp = 0; grp < 4; grp++) {
        u64 oA[8], oB[8];
#pragma unroll
        for (int jj = 0; jj < 8; jj++) { oA[jj] = 0ULL; oB[jj] = 0ULL; }
#pragma unroll
        for (int q = 0; q < 20; q += 2) {
            u64 a0 = hA[q], a1 = hA[q + 1];
            u64 b0 = hB[q], b1 = hB[q + 1];
#pragma unroll
            for (int jj = 0; jj < 8; jj++) {
                ulonglong2 w = ldc2(&WO2T[(grp * 8 + jj) * 20 + q]);
                oA[jj] = ffma2(a0, w.x, oA[jj]);
                oA[jj] = ffma2(a1, w.y, oA[jj]);
                oB[jj] = ffma2(b0, w.x, oB[jj]);
                oB[jj] = ffma2(b1, w.y, oB[jj]);
            }
        }

        // pack channel pairs, activate packed, merge A+B, reduce packed
        u64 pvB[4], m[4];
#pragma unroll
        for (int h2 = 0; h2 < 4; h2++) {
            float l0, h0, l1, h1;
            up2(oA[2 * h2], l0, h0);
            up2(oA[2 * h2 + 1], l1, h1);
            u64 pvA = plrelu2(pk2(l0 + h0, l1 + h1));
            up2(oB[2 * h2], l0, h0);
            up2(oB[2 * h2 + 1], l1, h1);
            pvB[h2] = plrelu2(pk2(l0 + h0, l1 + h1));
            m[h2] = same ? add2(pvA, pvB[h2]) : pvA;
        }
#pragma unroll
        for (int h2 = 0; h2 < 4; h2++) {
            u64 v = m[h2];
#pragma unroll
            for (int s = 0; s < 5; s++) {
                u64 sv = __shfl_down_sync(0xffffffffu, v, 1 << s);
                if (pd[s]) v = add2(v, sv);
            }
            m[h2] = v;
        }
        if (leader) {
#pragma unroll
            for (int h2 = 0; h2 < 4; h2++) {
                float lo, hi; up2(m[h2], lo, hi);
                red2(&g_pooled[bA * 32 + grp * 8 + 2 * h2], lo, hi);
            }
        }
        if (!same) {
#pragma unroll
            for (int h2 = 0; h2 < 4; h2++) {
                float lo, hi; up2(pvB[h2], lo, hi);
                red2(&g_pooled[bB * 32 + grp * 8 + 2 * h2], lo, hi);
            }
        }
    }
}

// =====================================================================
// Pass 4: out = ffn(pooled, Wd1, Wd2, final_linear=True)
// =====================================================================
__global__ void __launch_bounds__(256) k_disc(float* __restrict__ out) {
    int g = blockIdx.x * 256 + threadIdx.x;   // grid = NG/256 exactly
    float p[32];
#pragma unroll
    for (int j = 0; j < 32; j++) p[j] = g_pooled[g * 32 + j];

    u64 acc[20];
#pragma unroll
    for (int j = 0; j < 20; j++) acc[j] = 0ULL;
#pragma unroll
    for (int k = 0; k < 32; k++) {
        u64 a = pk2(p[k], p[k]);
#pragma unroll
        for (int q = 0; q < 20; q += 2) {
            ulonglong2 w = ldc2(&WD1[k * 20 + q]);
            acc[q]     = ffma2(a, w.x, acc[q]);
            acc[q + 1] = ffma2(a, w.y, acc[q + 1]);
        }
    }
    u64 s = 0ULL;
#pragma unroll
    for (int j = 0; j < 20; j += 2) {
        ulonglong2 w = ldc2(&WD2[j]);
        s = ffma2(plrelu2(acc[j]),     w.x, s);
        s = ffma2(plrelu2(acc[j + 1]), w.y, s);
    }
    float lo, hi; up2(s, lo, hi);
    out[g] = lo + hi;   // final_linear: no activation
}

extern "C" void kernel_launch(void* const* d_in, const int* in_sizes, int n_in,
                              void* d_out, int out_size) {
    const float* x     = (const float*)d_in[0];
    const int*   batch = (const int*)d_in[1];
    float* out = (float*)d_out;

    // Build the full weight image + zero g_aggr, then ONE constant upload
    k_pre<<<80, 256>>>((const float*)d_in[2], (const float*)d_in[3],
                       (const float*)d_in[4], (const float*)d_in[5],
                       (const float*)d_in[6], (const float*)d_in[7],
                       (const float*)d_in[8], (const float*)d_in[9]);
    void* pStage = nullptr;
    cudaGetSymbolAddress(&pStage, g_stage);
    cudaMemcpyToSymbolAsync(cAll, pStage, 1820 * 8, 0, cudaMemcpyDeviceToDevice, 0);

    const int nblk2 = (NPTS / 2 + 255) / 256;   // P=2 kernels
    k_emb<<<nblk2, 256>>>(x, batch);
    k_glob<<<NG / 256, 256>>>();
    k_out<<<nblk2, 256>>>(batch);
    k_disc<<<NG / 256, 256>>>(out);
}